// round 1
// baseline (speedup 1.0000x reference)
#include <cuda_runtime.h>
#include <cstdint>

#define N_NODES 100000
#define N_EDGES 1600000
#define C 32

// Scratch (allocations are forbidden; device globals are allowed)
__device__ float g_deg[N_NODES];
__device__ float g_dinv[N_NODES];
__device__ float4 g_hs[N_NODES * (C / 4)];   // hs[i] = (x[i] @ W^T) * dinv[i]

// ---------------------------------------------------------------------------
// K1: deg = 1 (self-loop contribution)
__global__ void k_init_deg() {
    int i = blockIdx.x * blockDim.x + threadIdx.x;
    if (i < N_NODES) g_deg[i] = 1.0f;
}

// K2: deg[col[e]] += 1
__global__ void k_count(const int* __restrict__ col) {
    int e = blockIdx.x * blockDim.x + threadIdx.x;
    if (e < N_EDGES) atomicAdd(&g_deg[col[e]], 1.0f);
}

// K3: dinv = rsqrt(deg); hs = (x @ W^T) * dinv; out = hs (self-loop term)
// Block = 256 threads = 8 nodes x 32 output channels.
__global__ void k_gemm(const float* __restrict__ x,
                       const float* __restrict__ W,
                       float* __restrict__ out) {
    __shared__ float Wsh[C][C + 1];   // Wsh[k][co] = W[co*C + k], padded
    int tid = threadIdx.x;
    // load 32x32 W, transposed
    #pragma unroll
    for (int i = tid; i < C * C; i += 256) {
        int co = i / C;
        int k  = i % C;
        Wsh[k][co] = W[co * C + k];
    }
    __syncthreads();

    int n  = blockIdx.x * 8 + (tid >> 5);
    int co = tid & 31;
    if (n >= N_NODES) return;

    float dinv = rsqrtf(g_deg[n]);
    if (co == 0) g_dinv[n] = dinv;

    const float* xr = x + n * C;
    float acc = 0.0f;
    #pragma unroll
    for (int k = 0; k < C; k++) {
        acc += __ldg(xr + k) * Wsh[k][co];
    }
    float hs = acc * dinv;
    reinterpret_cast<float*>(g_hs)[n * C + co] = hs;
    out[n * C + co] = hs;   // self-loop accumulator init
}

// K4: edge scatter — out[col] += hs[row], vector f32x4 RED atomics.
// 8 threads per edge, each owns one float4 channel group.
__global__ void k_scatter(const int* __restrict__ rowv,
                          const int* __restrict__ colv,
                          float* __restrict__ out) {
    int t = blockIdx.x * blockDim.x + threadIdx.x;
    int e = t >> 3;
    int g = t & 7;
    if (e >= N_EDGES) return;

    int r = __ldg(rowv + e);
    int c = __ldg(colv + e);
    float4 v = g_hs[r * 8 + g];
    float* dst = out + (size_t)c * C + g * 4;
    asm volatile("red.global.add.v4.f32 [%0], {%1, %2, %3, %4};"
                 :: "l"(dst), "f"(v.x), "f"(v.y), "f"(v.z), "f"(v.w)
                 : "memory");
}

// K5: out = out * dinv[node] + b[channel]
__global__ void k_final(float* __restrict__ out, const float* __restrict__ b) {
    int i = blockIdx.x * blockDim.x + threadIdx.x;
    if (i < N_NODES * C) {
        int n  = i >> 5;
        int co = i & 31;
        out[i] = out[i] * g_dinv[n] + __ldg(b + co);
    }
}

// ---------------------------------------------------------------------------
extern "C" void kernel_launch(void* const* d_in, const int* in_sizes, int n_in,
                              void* d_out, int out_size) {
    const float* x  = (const float*)d_in[0];
    const int*   ei = (const int*)d_in[1];        // [2, E]: row then col
    const float* W  = (const float*)d_in[2];
    const float* b  = (const float*)d_in[3];
    float* out = (float*)d_out;

    const int* rowv = ei;
    const int* colv = ei + N_EDGES;

    k_init_deg<<<(N_NODES + 255) / 256, 256>>>();
    k_count<<<(N_EDGES + 255) / 256, 256>>>(colv);
    k_gemm<<<(N_NODES + 7) / 8, 256>>>(x, W, out);
    k_scatter<<<(N_EDGES * 8 + 255) / 256, 256>>>(rowv, colv, out);
    k_final<<<(N_NODES * C + 255) / 256, 256>>>(out, b);
}